// round 3
// baseline (speedup 1.0000x reference)
#include <cuda_runtime.h>
#include <stdint.h>

#define Bc    64
#define CIN   256
#define COUT  256
#define HW    28
#define NPIX  (HW*HW)            // 784
#define NW    (COUT*CIN*9)       // 589824
#define KK    8
#define PDIM  30                 // padded spatial dim
#define PPIX  (PDIM*PDIM)        // 900
#define PROWS 960                // padded pixel rows per image (>= 957 reach)

// ---------------- device scratch ----------------
__device__ __align__(16) uint8_t g_act[(size_t)Bc * PROWS * CIN];   // s8 +-1 / 0 pad
__device__ __align__(16) uint8_t g_wf8[(size_t)COUT * 2304];        // s8 +-1, [o][t*256+c]

// ---------------- helpers ----------------
__device__ __forceinline__ uint32_t smem_u32(const void* p) {
    uint32_t a;
    asm("{ .reg .u64 t; cvta.to.shared.u64 t, %1; cvt.u32.u64 %0, t; }" : "=r"(a) : "l"(p));
    return a;
}
__device__ __forceinline__ void cp16(uint32_t dst, const void* src) {
    asm volatile("cp.async.cg.shared.global [%0], [%1], 16;\n" :: "r"(dst), "l"(src));
}
__device__ __forceinline__ void cp_commit() { asm volatile("cp.async.commit_group;\n"); }
__device__ __forceinline__ void cp_wait1()  { asm volatile("cp.async.wait_group 1;\n"); }
__device__ __forceinline__ void cp_wait0()  { asm volatile("cp.async.wait_group 0;\n"); }
__device__ __forceinline__ uint32_t sw128(uint32_t off) { return off ^ ((off >> 3) & 0x70); }

__device__ __forceinline__ void ldsm4(uint32_t* r, uint32_t addr) {
    asm volatile("ldmatrix.sync.aligned.m8n8.x4.shared.b16 {%0,%1,%2,%3}, [%4];"
                 : "=r"(r[0]), "=r"(r[1]), "=r"(r[2]), "=r"(r[3]) : "r"(addr));
}
__device__ __forceinline__ void imma16832(int* d, const uint32_t* a, uint32_t b0, uint32_t b1) {
    asm volatile("mma.sync.aligned.m16n8k32.row.col.s32.s8.s8.s32 "
                 "{%0,%1,%2,%3}, {%4,%5,%6,%7}, {%8,%9}, {%0,%1,%2,%3};"
                 : "+r"(d[0]), "+r"(d[1]), "+r"(d[2]), "+r"(d[3])
                 : "r"(a[0]), "r"(a[1]), "r"(a[2]), "r"(a[3]), "r"(b0), "r"(b1));
}

// ---------------------------------------------------------------------------
// Kernel 1: weights -> s8 sign bytes, layout [o][t*256 + c]
// grid <<<576, 256>>>, 4 flat elements per thread (float4 loads)
// ---------------------------------------------------------------------------
__global__ void wconv_kernel(const float* __restrict__ M, const float* __restrict__ Z,
                             const float* __restrict__ rv)
{
    const int gid = blockIdx.x * 256 + threadIdx.x;
    float rvl[KK];
#pragma unroll
    for (int k = 0; k < KK; k++) rvl[k] = __ldg(rv + k);

    const int idx4 = gid * 4;
    float4 w4 = *(const float4*)(M + idx4);
#pragma unroll
    for (int k = 0; k < KK; k++) {
        float4 z4 = *(const float4*)(Z + (size_t)k * NW + idx4);
        w4.x += rvl[k] * z4.x; w4.y += rvl[k] * z4.y;
        w4.z += rvl[k] * z4.z; w4.w += rvl[k] * z4.w;
    }
    float wv[4] = {w4.x, w4.y, w4.z, w4.w};
#pragma unroll
    for (int e = 0; e < 4; e++) {
        int flat = idx4 + e;
        int o = flat / 2304;
        int rem = flat - o * 2304;
        int c = rem / 9;
        int t = rem - c * 9;
        uint32_t s = __float_as_uint(wv[e]) >> 31;
        g_wf8[(size_t)o * 2304 + t * 256 + c] = (uint8_t)(0x01u + s * 0xFEu);
    }
}

// ---------------------------------------------------------------------------
// Kernel 2: activations -> zero-padded s8 sign image [b][pp][c]
// grid <<<225, 256>>>
// ---------------------------------------------------------------------------
__global__ void aconv_kernel(const float* __restrict__ x)
{
    const int gid = blockIdx.x * 256 + threadIdx.x;
    const int b  = gid / PPIX;
    const int pp = gid - b * PPIX;
    const int py = pp / PDIM;
    const int px = pp - py * PDIM;

    uint4* dst = (uint4*)(g_act + ((size_t)b * PROWS + pp) * CIN);

    if (py == 0 || py == PDIM - 1 || px == 0 || px == PDIM - 1) {
        uint4 z = make_uint4(0, 0, 0, 0);
#pragma unroll
        for (int i = 0; i < 16; i++) dst[i] = z;
        return;
    }
    const float* xp = x + (size_t)b * CIN * NPIX + (py - 1) * HW + (px - 1);
#pragma unroll
    for (int cw = 0; cw < 16; cw++) {
        uint32_t wds[4];
#pragma unroll
        for (int q = 0; q < 4; q++) {
            uint32_t wd = 0;
#pragma unroll
            for (int e = 0; e < 4; e++) {
                int c = cw * 16 + q * 4 + e;
                uint32_t s = __float_as_uint(xp[(size_t)c * NPIX]) >> 31;
                wd |= (0x01u + s * 0xFEu) << (8 * e);
            }
            wds[q] = wd;
        }
        dst[cw] = make_uint4(wds[0], wds[1], wds[2], wds[3]);
    }
}

// ---------------------------------------------------------------------------
// Kernel 3: s8 IMMA implicit-GEMM conv.
// CTA = (image b, M-tile of 128 padded pixels) x N=256 outch.
// K = 9 taps x 2 halves = 18 planes of 128 B, double-buffered cp.async.
// 16 warps; warp tile 32(M) x 64(N); mma.m16n8k32.s8 + ldmatrix.
// grid <<<448, 512, 99328>>>
// ---------------------------------------------------------------------------
#define SM_A0    0
#define SM_A1    16384
#define SM_B0    32768
#define SM_B1    65536
#define SM_ALPHA 98304
#define SM_TOTAL (98304 + 1024)

__global__ void __launch_bounds__(512, 1)
conv_imma_kernel(const float* __restrict__ alpha, float* __restrict__ out)
{
    extern __shared__ __align__(1024) uint8_t smem[];
    const uint32_t sb = smem_u32(smem);

    const int tid  = threadIdx.x;
    const int wid  = tid >> 5;
    const int lane = tid & 31;
    const int wm   = wid & 3;          // M-warp (32 pixels)
    const int wn   = wid >> 2;         // N-warp (64 outch)

    const int b     = blockIdx.x / 7;
    const int mtile = blockIdx.x - b * 7;
    const int tbase = mtile * 128;

    float* salpha = (float*)(smem + SM_ALPHA);
    if (tid < 256) salpha[tid] = __ldg(alpha + tid);

    const uint8_t* actb = g_act + (size_t)b * PROWS * CIN;

    int acc[2][8][4];
#pragma unroll
    for (int mf = 0; mf < 2; mf++)
#pragma unroll
        for (int nf = 0; nf < 8; nf++)
#pragma unroll
            for (int j = 0; j < 4; j++) acc[mf][nf][j] = 0;

    // ---- plane loader ----
    auto load_plane = [&](int p) {
        const int t = p >> 1, h = p & 1, buf = p & 1;
        const uint32_t ab = sb + (buf ? SM_A1 : SM_A0);
        const uint32_t bb = sb + (buf ? SM_B1 : SM_B0);
        const int toff = (t / 3) * PDIM + (t % 3);
        const uint8_t* asrc = actb + (size_t)(tbase + toff) * CIN + h * 128;
        const uint8_t* bsrc = g_wf8 + t * 256 + h * 128;
#pragma unroll
        for (int j = 0; j < 2; j++) {                 // A: 1024 chunks
            int idx = tid + j * 512;
            int r = idx >> 3, c = idx & 7;
            cp16(ab + sw128(r * 128 + c * 16), asrc + (size_t)r * CIN + c * 16);
        }
#pragma unroll
        for (int j = 0; j < 4; j++) {                 // B: 2048 chunks
            int idx = tid + j * 512;
            int r = idx >> 3, c = idx & 7;
            cp16(bb + sw128(r * 128 + c * 16), bsrc + (size_t)r * 2304 + c * 16);
        }
        cp_commit();
    };

    load_plane(0);

    const int lrow = lane & 15;
    const int lhi  = (lane >> 4) * 16;

    for (int p = 0; p < 18; ++p) {
        if (p < 17) { load_plane(p + 1); cp_wait1(); }
        else        { cp_wait0(); }
        __syncthreads();

        const int buf = p & 1;
        const uint32_t ab = sb + (buf ? SM_A1 : SM_A0);
        const uint32_t bb = sb + (buf ? SM_B1 : SM_B0);

#pragma unroll
        for (int ks = 0; ks < 4; ks++) {
            const int kcol = ks * 32 + lhi;
            uint32_t a[2][4];
#pragma unroll
            for (int mf = 0; mf < 2; mf++)
                ldsm4(a[mf], ab + sw128((wm * 32 + mf * 16 + lrow) * 128 + kcol));
            uint32_t bf[4][4];
#pragma unroll
            for (int bg = 0; bg < 4; bg++)
                ldsm4(bf[bg], bb + sw128((wn * 64 + bg * 16 + lrow) * 128 + kcol));
#pragma unroll
            for (int mf = 0; mf < 2; mf++)
#pragma unroll
                for (int nf = 0; nf < 8; nf++)
                    imma16832(acc[mf][nf], a[mf],
                              bf[nf >> 1][nf & 1], bf[nf >> 1][(nf & 1) + 2]);
        }
        __syncthreads();
    }

    // ---- epilogue: direct stores, x alpha ----
    const int pixr  = tbase + wm * 32;
    const int obase = wn * 64 + (lane & 3) * 2;
    float* outb = out + (size_t)b * COUT * NPIX;

#pragma unroll
    for (int mf = 0; mf < 2; mf++) {
        const int rb = pixr + mf * 16 + (lane >> 2);
#pragma unroll
        for (int half = 0; half < 2; half++) {
            const int row = rb + half * 8;
            const int y  = row / PDIM;
            const int xx = row - y * PDIM;
            if (xx < HW && y < HW) {
                float* op = outb + y * HW + xx;
#pragma unroll
                for (int nf = 0; nf < 8; nf++) {
                    const int o = obase + nf * 8;
                    op[(size_t)o * NPIX]       = salpha[o]     * (float)acc[mf][nf][half * 2];
                    op[(size_t)(o + 1) * NPIX] = salpha[o + 1] * (float)acc[mf][nf][half * 2 + 1];
                }
            }
        }
    }
}

// ---------------------------------------------------------------------------
extern "C" void kernel_launch(void* const* d_in, const int* in_sizes, int n_in,
                              void* d_out, int out_size)
{
    const float* x  = (const float*)d_in[0];
    const float* M  = (const float*)d_in[1];
    const float* Z  = (const float*)d_in[2];
    const float* al = (const float*)d_in[3];
    const float* rv = (const float*)d_in[4];

    cudaFuncSetAttribute(conv_imma_kernel,
                         cudaFuncAttributeMaxDynamicSharedMemorySize, SM_TOTAL);

    wconv_kernel<<<576, 256>>>(M, Z, rv);
    aconv_kernel<<<225, 256>>>(x);
    conv_imma_kernel<<<Bc * 7, 512, SM_TOTAL>>>(al, (float*)d_out);
}

// round 4
// speedup vs baseline: 1.0352x; 1.0352x over previous
#include <cuda_runtime.h>
#include <stdint.h>

#define Bc    64
#define CIN   256
#define COUT  256
#define HW    28
#define NPIX  (HW*HW)            // 784
#define NW    (COUT*CIN*9)       // 589824
#define KK    8
#define PDIM  30                 // padded spatial dim
#define PPIX  (PDIM*PDIM)        // 900
#define PROWS 960                // padded pixel rows per image

// ---------------- device scratch ----------------
__device__ __align__(16) uint8_t g_act[(size_t)Bc * PROWS * CIN];   // s8 +-1 / 0 pad
__device__ __align__(16) uint8_t g_wf8[(size_t)COUT * 2304];        // s8 +-1, [o][t*256+c]

// ---------------- helpers ----------------
__device__ __forceinline__ uint32_t smem_u32(const void* p) {
    uint32_t a;
    asm("{ .reg .u64 t; cvta.to.shared.u64 t, %1; cvt.u32.u64 %0, t; }" : "=r"(a) : "l"(p));
    return a;
}
__device__ __forceinline__ void cp16(uint32_t dst, const void* src) {
    asm volatile("cp.async.cg.shared.global [%0], [%1], 16;\n" :: "r"(dst), "l"(src));
}
__device__ __forceinline__ void cp_commit() { asm volatile("cp.async.commit_group;\n"); }
__device__ __forceinline__ void cp_wait1()  { asm volatile("cp.async.wait_group 1;\n"); }
__device__ __forceinline__ void cp_wait0()  { asm volatile("cp.async.wait_group 0;\n"); }
__device__ __forceinline__ uint32_t sw128(uint32_t off) { return off ^ ((off >> 3) & 0x70); }

__device__ __forceinline__ void ldsm4(uint32_t* r, uint32_t addr) {
    asm volatile("ldmatrix.sync.aligned.m8n8.x4.shared.b16 {%0,%1,%2,%3}, [%4];"
                 : "=r"(r[0]), "=r"(r[1]), "=r"(r[2]), "=r"(r[3]) : "r"(addr));
}
__device__ __forceinline__ void imma16832(int* d, const uint32_t* a, uint32_t b0, uint32_t b1) {
    asm volatile("mma.sync.aligned.m16n8k32.row.col.s32.s8.s8.s32 "
                 "{%0,%1,%2,%3}, {%4,%5,%6,%7}, {%8,%9}, {%0,%1,%2,%3};"
                 : "+r"(d[0]), "+r"(d[1]), "+r"(d[2]), "+r"(d[3])
                 : "r"(a[0]), "r"(a[1]), "r"(a[2]), "r"(a[3]), "r"(b0), "r"(b1));
}

// ---------------------------------------------------------------------------
// Kernel 1: weights -> s8 sign bytes, layout [o][t*256 + c]
// ---------------------------------------------------------------------------
__global__ void wconv_kernel(const float* __restrict__ M, const float* __restrict__ Z,
                             const float* __restrict__ rv)
{
    const int gid = blockIdx.x * 256 + threadIdx.x;
    float rvl[KK];
#pragma unroll
    for (int k = 0; k < KK; k++) rvl[k] = __ldg(rv + k);

    const int idx4 = gid * 4;
    float4 w4 = *(const float4*)(M + idx4);
#pragma unroll
    for (int k = 0; k < KK; k++) {
        float4 z4 = *(const float4*)(Z + (size_t)k * NW + idx4);
        w4.x += rvl[k] * z4.x; w4.y += rvl[k] * z4.y;
        w4.z += rvl[k] * z4.z; w4.w += rvl[k] * z4.w;
    }
    float wv[4] = {w4.x, w4.y, w4.z, w4.w};
#pragma unroll
    for (int e = 0; e < 4; e++) {
        int flat = idx4 + e;
        int o = flat / 2304;
        int rem = flat - o * 2304;
        int c = rem / 9;
        int t = rem - c * 9;
        uint32_t s = __float_as_uint(wv[e]) >> 31;
        g_wf8[(size_t)o * 2304 + t * 256 + c] = (uint8_t)(0x01u + s * 0xFEu);
    }
}

// ---------------------------------------------------------------------------
// Kernel 2: activations -> zero-padded s8 sign image [b][pp][c]
// ---------------------------------------------------------------------------
__global__ void aconv_kernel(const float* __restrict__ x)
{
    const int gid = blockIdx.x * 256 + threadIdx.x;
    const int b  = gid / PPIX;
    const int pp = gid - b * PPIX;
    const int py = pp / PDIM;
    const int px = pp - py * PDIM;

    uint4* dst = (uint4*)(g_act + ((size_t)b * PROWS + pp) * CIN);

    if (py == 0 || py == PDIM - 1 || px == 0 || px == PDIM - 1) {
        uint4 z = make_uint4(0, 0, 0, 0);
#pragma unroll
        for (int i = 0; i < 16; i++) dst[i] = z;
        return;
    }
    const float* xp = x + (size_t)b * CIN * NPIX + (py - 1) * HW + (px - 1);
#pragma unroll
    for (int cw = 0; cw < 16; cw++) {
        uint32_t wds[4];
#pragma unroll
        for (int q = 0; q < 4; q++) {
            uint32_t wd = 0;
#pragma unroll
            for (int e = 0; e < 4; e++) {
                int c = cw * 16 + q * 4 + e;
                uint32_t s = __float_as_uint(xp[(size_t)c * NPIX]) >> 31;
                wd |= (0x01u + s * 0xFEu) << (8 * e);
            }
            wds[q] = wd;
        }
        dst[cw] = make_uint4(wds[0], wds[1], wds[2], wds[3]);
    }
}

// ---------------------------------------------------------------------------
// Kernel 3: s8 IMMA implicit-GEMM conv.
// CTA = (image b, 128-pixel M-tile, 128-outch N-half).
// 8 warps (256 thr), warp tile 32(M) x 64(N); regs ~115 -> no spill.
// K = 18 planes of 128 B, double-buffered cp.async.
// grid <<<896, 256, 66560>>>
// ---------------------------------------------------------------------------
#define SM_A0    0
#define SM_A1    16384
#define SM_B0    32768
#define SM_B1    49152
#define SM_ALPHA 65536
#define SM_TOTAL (65536 + 1024)

__global__ void __launch_bounds__(256)
conv_imma_kernel(const float* __restrict__ alpha, float* __restrict__ out)
{
    extern __shared__ __align__(1024) uint8_t smem[];
    const uint32_t sb = smem_u32(smem);

    const int tid  = threadIdx.x;
    const int wid  = tid >> 5;
    const int lane = tid & 31;
    const int wm   = wid & 3;          // M-warp (32 pixels)
    const int wn   = wid >> 2;         // N-warp (64 outch), 0..1

    const int nh    = blockIdx.x & 1;                  // N half
    const int bm    = blockIdx.x >> 1;
    const int b     = bm / 7;
    const int mtile = bm - b * 7;
    const int tbase = mtile * 128;

    float* salpha = (float*)(smem + SM_ALPHA);
    salpha[tid] = __ldg(alpha + nh * 128 + (tid & 127));

    const uint8_t* actb = g_act + (size_t)b * PROWS * CIN;
    const uint8_t* wb   = g_wf8 + (size_t)nh * 128 * 2304;

    int acc[2][8][4];
#pragma unroll
    for (int mf = 0; mf < 2; mf++)
#pragma unroll
        for (int nf = 0; nf < 8; nf++)
#pragma unroll
            for (int j = 0; j < 4; j++) acc[mf][nf][j] = 0;

    // ---- plane loader: A 16KB + B 16KB ----
    auto load_plane = [&](int p) {
        const int t = p >> 1, h = p & 1, buf = p & 1;
        const uint32_t ab = sb + (buf ? SM_A1 : SM_A0);
        const uint32_t bb = sb + (buf ? SM_B1 : SM_B0);
        const int toff = (t / 3) * PDIM + (t % 3);
        const uint8_t* asrc = actb + (size_t)(tbase + toff) * CIN + h * 128;
        const uint8_t* bsrc = wb + t * 256 + h * 128;
#pragma unroll
        for (int j = 0; j < 4; j++) {                 // A: 1024 chunks
            int idx = tid + j * 256;
            int r = idx >> 3, c = idx & 7;
            cp16(ab + sw128(r * 128 + c * 16), asrc + (size_t)r * CIN + c * 16);
        }
#pragma unroll
        for (int j = 0; j < 4; j++) {                 // B: 1024 chunks
            int idx = tid + j * 256;
            int r = idx >> 3, c = idx & 7;
            cp16(bb + sw128(r * 128 + c * 16), bsrc + (size_t)r * 2304 + c * 16);
        }
        cp_commit();
    };

    load_plane(0);

    const int lrow = lane & 15;
    const int lhi  = (lane >> 4) * 16;

    for (int p = 0; p < 18; ++p) {
        if (p < 17) { load_plane(p + 1); cp_wait1(); }
        else        { cp_wait0(); }
        __syncthreads();

        const int buf = p & 1;
        const uint32_t ab = sb + (buf ? SM_A1 : SM_A0);
        const uint32_t bb = sb + (buf ? SM_B1 : SM_B0);

#pragma unroll
        for (int ks = 0; ks < 4; ks++) {
            const int kcol = ks * 32 + lhi;
            uint32_t a[2][4];
#pragma unroll
            for (int mf = 0; mf < 2; mf++)
                ldsm4(a[mf], ab + sw128((wm * 32 + mf * 16 + lrow) * 128 + kcol));
            uint32_t bf[4][4];
#pragma unroll
            for (int bg = 0; bg < 4; bg++)
                ldsm4(bf[bg], bb + sw128((wn * 64 + bg * 16 + lrow) * 128 + kcol));
#pragma unroll
            for (int mf = 0; mf < 2; mf++)
#pragma unroll
                for (int nf = 0; nf < 8; nf++)
                    imma16832(acc[mf][nf], a[mf],
                              bf[nf >> 1][nf & 1], bf[nf >> 1][(nf & 1) + 2]);
        }
        __syncthreads();
    }

    // ---- epilogue: direct stores, x alpha ----
    const int pixr   = tbase + wm * 32;
    const int oloc   = wn * 64 + (lane & 3) * 2;       // local outch in [0,128)
    const int oglob  = nh * 128 + oloc;
    float* outb = out + (size_t)b * COUT * NPIX;

#pragma unroll
    for (int mf = 0; mf < 2; mf++) {
        const int rb = pixr + mf * 16 + (lane >> 2);
#pragma unroll
        for (int half = 0; half < 2; half++) {
            const int row = rb + half * 8;
            const int y  = row / PDIM;
            const int xx = row - y * PDIM;
            if (xx < HW && y < HW) {
                float* op = outb + y * HW + xx;
#pragma unroll
                for (int nf = 0; nf < 8; nf++) {
                    const int ol = oloc + nf * 8;
                    const int og = oglob + nf * 8;
                    op[(size_t)og * NPIX]       = salpha[ol]     * (float)acc[mf][nf][half * 2];
                    op[(size_t)(og + 1) * NPIX] = salpha[ol + 1] * (float)acc[mf][nf][half * 2 + 1];
                }
            }
        }
    }
}

// ---------------------------------------------------------------------------
extern "C" void kernel_launch(void* const* d_in, const int* in_sizes, int n_in,
                              void* d_out, int out_size)
{
    const float* x  = (const float*)d_in[0];
    const float* M  = (const float*)d_in[1];
    const float* Z  = (const float*)d_in[2];
    const float* al = (const float*)d_in[3];
    const float* rv = (const float*)d_in[4];

    cudaFuncSetAttribute(conv_imma_kernel,
                         cudaFuncAttributeMaxDynamicSharedMemorySize, SM_TOTAL);

    wconv_kernel<<<576, 256>>>(M, Z, rv);
    aconv_kernel<<<225, 256>>>(x);
    conv_imma_kernel<<<Bc * 7 * 2, 256, SM_TOTAL>>>(al, (float*)d_out);
}

// round 5
// speedup vs baseline: 1.0468x; 1.0113x over previous
#include <cuda_runtime.h>
#include <stdint.h>

#define Bc    64
#define CIN   256
#define COUT  256
#define HW    28
#define NPIX  (HW*HW)            // 784
#define NW    (COUT*CIN*9)       // 589824
#define KK    8
#define PDIM  30                 // padded spatial dim
#define PPIX  (PDIM*PDIM)        // 900
#define PROWS 960                // padded pixel rows per image

// ---------------- device scratch ----------------
// Activations: [b][pp][256 bytes], 16B chunk index XOR-swizzled by (pp & 7)
__device__ __align__(1024) uint8_t g_act[(size_t)Bc * PROWS * CIN];
// Weights: per plane (t,h): [o][128 bytes], chunk index XOR-swizzled by (o & 7)
__device__ __align__(1024) uint8_t g_wB[(size_t)18 * 256 * 128];

// ---------------- helpers ----------------
__device__ __forceinline__ uint32_t smem_u32(const void* p) {
    uint32_t a;
    asm("{ .reg .u64 t; cvta.to.shared.u64 t, %1; cvt.u32.u64 %0, t; }" : "=r"(a) : "l"(p));
    return a;
}
__device__ __forceinline__ void mbar_init(uint32_t mb, uint32_t cnt) {
    asm volatile("mbarrier.init.shared.b64 [%0], %1;" :: "r"(mb), "r"(cnt) : "memory");
}
__device__ __forceinline__ void mbar_expect_tx(uint32_t mb, uint32_t bytes) {
    asm volatile("mbarrier.arrive.expect_tx.shared.b64 _, [%0], %1;" :: "r"(mb), "r"(bytes) : "memory");
}
__device__ __forceinline__ void mbar_wait(uint32_t mb, uint32_t parity) {
    asm volatile(
        "{\n"
        ".reg .pred P1;\n"
        "LAB_WAIT_%=:\n"
        "mbarrier.try_wait.parity.acquire.cta.shared::cta.b64 P1, [%0], %1, 0x989680;\n"
        "@P1 bra.uni LAB_DONE_%=;\n"
        "bra.uni LAB_WAIT_%=;\n"
        "LAB_DONE_%=:\n"
        "}\n" :: "r"(mb), "r"(parity) : "memory");
}
__device__ __forceinline__ void bulk_g2s(uint32_t dst, const void* src, uint32_t bytes, uint32_t mb) {
    asm volatile("cp.async.bulk.shared::cta.global.mbarrier::complete_tx::bytes [%0], [%1], %2, [%3];"
                 :: "r"(dst), "l"(src), "r"(bytes), "r"(mb) : "memory");
}
__device__ __forceinline__ void ldsm4(uint32_t* r, uint32_t addr) {
    asm volatile("ldmatrix.sync.aligned.m8n8.x4.shared.b16 {%0,%1,%2,%3}, [%4];"
                 : "=r"(r[0]), "=r"(r[1]), "=r"(r[2]), "=r"(r[3]) : "r"(addr));
}
__device__ __forceinline__ void imma16832(int* d, const uint32_t* a, uint32_t b0, uint32_t b1) {
    asm volatile("mma.sync.aligned.m16n8k32.row.col.s32.s8.s8.s32 "
                 "{%0,%1,%2,%3}, {%4,%5,%6,%7}, {%8,%9}, {%0,%1,%2,%3};"
                 : "+r"(d[0]), "+r"(d[1]), "+r"(d[2]), "+r"(d[3])
                 : "r"(a[0]), "r"(a[1]), "r"(a[2]), "r"(a[3]), "r"(b0), "r"(b1));
}

// ---------------------------------------------------------------------------
// Kernel 1: weights -> s8 sign bytes into plane layout
// g_wB[((t*2+h)*256 + o)*128 + ((kc16 ^ (o&7))<<4) + e]
// ---------------------------------------------------------------------------
__global__ void wconv_kernel(const float* __restrict__ M, const float* __restrict__ Z,
                             const float* __restrict__ rv)
{
    const int gid = blockIdx.x * 256 + threadIdx.x;
    float rvl[KK];
#pragma unroll
    for (int k = 0; k < KK; k++) rvl[k] = __ldg(rv + k);

    const int idx4 = gid * 4;
    float4 w4 = *(const float4*)(M + idx4);
#pragma unroll
    for (int k = 0; k < KK; k++) {
        float4 z4 = *(const float4*)(Z + (size_t)k * NW + idx4);
        w4.x += rvl[k] * z4.x; w4.y += rvl[k] * z4.y;
        w4.z += rvl[k] * z4.z; w4.w += rvl[k] * z4.w;
    }
    float wv[4] = {w4.x, w4.y, w4.z, w4.w};
#pragma unroll
    for (int e4 = 0; e4 < 4; e4++) {
        int flat = idx4 + e4;
        int o = flat / 2304;
        int rem = flat - o * 2304;
        int c = rem / 9;
        int t = rem - c * 9;
        uint32_t s = __float_as_uint(wv[e4]) >> 31;
        const int h    = c >> 7;
        const int kc16 = (c >> 4) & 7;
        const int e    = c & 15;
        const size_t off = ((size_t)((t * 2 + h) * 256 + o)) * 128
                         + (uint32_t)(((kc16 ^ (o & 7)) << 4) + e);
        g_wB[off] = (uint8_t)(0x01u + s * 0xFEu);
    }
}

// ---------------------------------------------------------------------------
// Kernel 2: activations -> zero-padded s8 image [b][pp][256], chunks swizzled
// ---------------------------------------------------------------------------
__global__ void aconv_kernel(const float* __restrict__ x)
{
    const int gid = blockIdx.x * 256 + threadIdx.x;
    const int b  = gid / PPIX;
    const int pp = gid - b * PPIX;
    const int py = pp / PDIM;
    const int px = pp - py * PDIM;

    uint4* dst = (uint4*)(g_act + ((size_t)b * PROWS + pp) * CIN);

    if (py == 0 || py == PDIM - 1 || px == 0 || px == PDIM - 1) {
        uint4 z = make_uint4(0, 0, 0, 0);
#pragma unroll
        for (int i = 0; i < 16; i++) dst[i] = z;
        return;
    }
    const int sw = pp & 7;
    const float* xp = x + (size_t)b * CIN * NPIX + (py - 1) * HW + (px - 1);
#pragma unroll
    for (int cw = 0; cw < 16; cw++) {
        uint32_t wds[4];
#pragma unroll
        for (int q = 0; q < 4; q++) {
            uint32_t wd = 0;
#pragma unroll
            for (int e = 0; e < 4; e++) {
                int c = cw * 16 + q * 4 + e;
                uint32_t s = __float_as_uint(xp[(size_t)c * NPIX]) >> 31;
                wd |= (0x01u + s * 0xFEu) << (8 * e);
            }
            wds[q] = wd;
        }
        dst[cw ^ sw] = make_uint4(wds[0], wds[1], wds[2], wds[3]);
    }
}

// ---------------------------------------------------------------------------
// Kernel 3: s8 IMMA implicit-GEMM conv with cp.async.bulk staging.
// CTA = (image b, 128-pixel M-tile, 128-outch N-half). 8 warps.
// A: one 48.6KB bulk (rows tbase..tbase+189 cover all 9 taps).
// B: 18 planes x 16KB bulk, double-buffered, mbarrier pipelined.
// grid <<<896, 256, 82560>>>
// ---------------------------------------------------------------------------
#define SM_A     0                    // 192 rows x 256 = 49152
#define SM_B0    49152                // 16384
#define SM_B1    65536                // 16384
#define SM_ALPHA 81920                // 512
#define SM_MBAR  82432                // 3 x 8
#define SM_TOTAL 82560

__global__ void __launch_bounds__(256)
conv_imma_kernel(const float* __restrict__ alpha, float* __restrict__ out)
{
    extern __shared__ __align__(1024) uint8_t smem[];
    const uint32_t sb = smem_u32(smem);

    const int tid  = threadIdx.x;
    const int wid  = tid >> 5;
    const int lane = tid & 31;
    const int wm   = wid & 3;          // M-warp (32 pixels)
    const int wn   = wid >> 2;         // N-warp (64 outch), 0..1

    const int nh    = blockIdx.x & 1;                  // N half
    const int bm    = blockIdx.x >> 1;
    const int b     = bm / 7;
    const int mtile = bm - b * 7;
    const int tbase = mtile * 128;

    const uint32_t mbA = sb + SM_MBAR;
    const uint32_t mbB = sb + SM_MBAR + 8;             // +8*buf

    float* salpha = (float*)(smem + SM_ALPHA);
    if (tid == 0) { mbar_init(mbA, 1); mbar_init(mbB, 1); mbar_init(mbB + 8, 1); }
    if (tid < 128) salpha[tid] = __ldg(alpha + nh * 128 + tid);
    __syncthreads();

    if (tid == 0) {
        mbar_expect_tx(mbA, 190 * 256);
        bulk_g2s(sb + SM_A, g_act + ((size_t)b * PROWS + tbase) * 256, 190 * 256, mbA);
        mbar_expect_tx(mbB, 16384);
        bulk_g2s(sb + SM_B0, g_wB + (size_t)(0 * 256 + nh * 128) * 128, 16384, mbB);
    }

    int acc[2][8][4];
#pragma unroll
    for (int mf = 0; mf < 2; mf++)
#pragma unroll
        for (int nf = 0; nf < 8; nf++)
#pragma unroll
            for (int j = 0; j < 4; j++) acc[mf][nf][j] = 0;

    const int lrow = lane & 15;
    const int lhi4 = lane >> 4;        // 16B chunk select within 32B k-group

    for (int p = 0; p < 18; ++p) {
        const int buf = p & 1;
        // issue next plane into the other buffer (safe: consumed 2 planes ago,
        // __syncthreads at end of plane p-1 ordered all its reads)
        if (p < 17 && tid == 0) {
            const int pn = p + 1;
            const uint32_t mb = mbB + (pn & 1) * 8;
            mbar_expect_tx(mb, 16384);
            bulk_g2s(sb + ((pn & 1) ? SM_B1 : SM_B0),
                     g_wB + (size_t)(pn * 256 + nh * 128) * 128, 16384, mb);
        }
        mbar_wait(mbB + buf * 8, (p >> 1) & 1);
        if (p == 0) mbar_wait(mbA, 0);

        const int t = p >> 1, h = p & 1;
        const int toff = (t / 3) * PDIM + (t % 3);
        const uint32_t bb = sb + (buf ? SM_B1 : SM_B0);

#pragma unroll
        for (int ks = 0; ks < 4; ks++) {
            uint32_t a[2][4];
#pragma unroll
            for (int mf = 0; mf < 2; mf++) {
                const int row = toff + wm * 32 + mf * 16 + lrow;
                const int c16 = h * 8 + ks * 2 + lhi4;
                ldsm4(a[mf], sb + SM_A + row * 256 + ((c16 ^ (row & 7)) << 4));
            }
            uint32_t bf[4][4];
#pragma unroll
            for (int bg = 0; bg < 4; bg++) {
                const int o  = wn * 64 + bg * 16 + lrow;
                const int kc = ks * 2 + lhi4;
                ldsm4(bf[bg], bb + o * 128 + ((kc ^ (o & 7)) << 4));
            }
#pragma unroll
            for (int mf = 0; mf < 2; mf++)
#pragma unroll
                for (int nf = 0; nf < 8; nf++)
                    imma16832(acc[mf][nf], a[mf],
                              bf[nf >> 1][nf & 1], bf[nf >> 1][(nf & 1) + 2]);
        }
        __syncthreads();
    }

    // ---- epilogue: direct stores, x alpha ----
    const int pixr  = tbase + wm * 32;
    const int oloc  = wn * 64 + (lane & 3) * 2;        // local outch in [0,128)
    const int oglob = nh * 128 + oloc;
    float* outb = out + (size_t)b * COUT * NPIX;

#pragma unroll
    for (int mf = 0; mf < 2; mf++) {
        const int rb = pixr + mf * 16 + (lane >> 2);
#pragma unroll
        for (int half = 0; half < 2; half++) {
            const int row = rb + half * 8;
            const int y  = row / PDIM;
            const int xx = row - y * PDIM;
            if (xx < HW && y < HW) {
                float* op = outb + y * HW + xx;
#pragma unroll
                for (int nf = 0; nf < 8; nf++) {
                    const int ol = oloc + nf * 8;
                    const int og = oglob + nf * 8;
                    op[(size_t)og * NPIX]       = salpha[ol]     * (float)acc[mf][nf][half * 2];
                    op[(size_t)(og + 1) * NPIX] = salpha[ol + 1] * (float)acc[mf][nf][half * 2 + 1];
                }
            }
        }
    }
}

// ---------------------------------------------------------------------------
extern "C" void kernel_launch(void* const* d_in, const int* in_sizes, int n_in,
                              void* d_out, int out_size)
{
    const float* x  = (const float*)d_in[0];
    const float* M  = (const float*)d_in[1];
    const float* Z  = (const float*)d_in[2];
    const float* al = (const float*)d_in[3];
    const float* rv = (const float*)d_in[4];

    cudaFuncSetAttribute(conv_imma_kernel,
                         cudaFuncAttributeMaxDynamicSharedMemorySize, SM_TOTAL);

    wconv_kernel<<<576, 256>>>(M, Z, rv);
    aconv_kernel<<<225, 256>>>(x);
    conv_imma_kernel<<<Bc * 7 * 2, 256, SM_TOTAL>>>(al, (float*)d_out);
}

// round 6
// speedup vs baseline: 2.2106x; 2.1117x over previous
#include <cuda_runtime.h>
#include <stdint.h>

#define Bc    64
#define CIN   256
#define COUT  256
#define HW    28
#define NPIX  (HW*HW)            // 784
#define NW    (COUT*CIN*9)       // 589824
#define KK    8
#define PDIM  30
#define PPIX  (PDIM*PDIM)        // 900

// ---------------- device scratch ----------------
__device__ __align__(16) uint32_t g_w[COUT * 9 * 8];          // [o][t][cw] sign bits
__device__ int                    g_corr[COUT * 9];           // 256 - 2*popc(w[o][t])
__device__ __align__(16) uint32_t g_pabits[(size_t)Bc * PPIX * 8]; // padded bit image

// ---------------------------------------------------------------------------
// Kernel 1: weights -> packed sign bits + per-(o,t) pad correction.
// grid <<<256, 256>>> (o = block, c = thread)
// ---------------------------------------------------------------------------
__global__ void wbits_kernel(const float* __restrict__ M, const float* __restrict__ Z,
                             const float* __restrict__ rv)
{
    __shared__ int sP[9];
    const int o    = blockIdx.x;
    const int c    = threadIdx.x;
    const int lane = c & 31;
    const int cw   = c >> 5;

    if (c < 9) sP[c] = 0;
    __syncthreads();

    float rvl[KK];
#pragma unroll
    for (int k = 0; k < KK; k++) rvl[k] = __ldg(rv + k);

    const int base = (o * CIN + c) * 9;
    float wv[9];
#pragma unroll
    for (int j = 0; j < 9; j++) wv[j] = M[base + j];
#pragma unroll
    for (int k = 0; k < KK; k++) {
        const float* zp = Z + (size_t)k * NW + base;
#pragma unroll
        for (int j = 0; j < 9; j++) wv[j] += rvl[k] * zp[j];
    }

#pragma unroll
    for (int j = 0; j < 9; j++) {
        unsigned bit  = __float_as_uint(wv[j]) >> 31;
        unsigned mask = __ballot_sync(0xffffffffu, bit);
        if (lane == 0) {
            g_w[(o * 9 + j) * 8 + cw] = mask;
            atomicAdd(&sP[j], __popc(mask));
        }
    }
    __syncthreads();
    if (c < 9) g_corr[o * 9 + c] = 256 - 2 * sP[c];
}

// ---------------------------------------------------------------------------
// Kernel 2: activations -> zero-padded packed bit image [b][pp][8]
// grid <<<225, 256>>>
// ---------------------------------------------------------------------------
__global__ void abits_kernel(const float* __restrict__ x)
{
    const int gid = blockIdx.x * 256 + threadIdx.x;
    const int b  = gid / PPIX;
    const int pp = gid - b * PPIX;
    const int py = pp / PDIM;
    const int px = pp - py * PDIM;

    uint4* dst = (uint4*)(g_pabits + ((size_t)b * PPIX + pp) * 8);

    if (py == 0 || py == PDIM - 1 || px == 0 || px == PDIM - 1) {
        uint4 z = make_uint4(0, 0, 0, 0);
        dst[0] = z; dst[1] = z;
        return;
    }
    const float* xp = x + (size_t)b * CIN * NPIX + (py - 1) * HW + (px - 1);
    uint32_t w[8];
#pragma unroll
    for (int cw = 0; cw < 8; cw++) {
        uint32_t m = 0;
#pragma unroll
        for (int j = 0; j < 32; j++) {
            uint32_t s = __float_as_uint(xp[(size_t)(cw * 32 + j) * NPIX]) >> 31;
            m |= s << j;
        }
        w[cw] = m;
    }
    dst[0] = make_uint4(w[0], w[1], w[2], w[3]);
    dst[1] = make_uint4(w[4], w[5], w[6], w[7]);
}

// ---------------------------------------------------------------------------
// Kernel 3: XNOR-popcount conv over the padded image, branch-free inner body.
// CTA = (image b, 4-row band). 8 warps; warp = 32-outch group, lane = outch.
// grid <<<448, 256, 35456>>>
// ---------------------------------------------------------------------------
#define SM_ABITS 0                      // 6 rows x 30 px x 32B = 5760
#define SM_STAGE 5760                   // 8 warps x 32 x 29 floats = 29696
#define SM_TOTAL (5760 + 29696)

__global__ void __launch_bounds__(256)
conv_pop_kernel(const float* __restrict__ alpha, float* __restrict__ out)
{
    extern __shared__ __align__(16) uint8_t smem[];

    const int tid  = threadIdx.x;
    const int wid  = tid >> 5;
    const int lane = tid & 31;

    const int b      = blockIdx.x / 7;
    const int blkrow = blockIdx.x - b * 7;
    const int r0     = blkrow * 4;        // first output row of this band

    // cooperative load: padded rows r0..r0+5 (contiguous in g_pabits)
    {
        const uint4* src = (const uint4*)(g_pabits + ((size_t)b * PPIX + r0 * PDIM) * 8);
        uint4* d4 = (uint4*)(smem + SM_ABITS);
        for (int i = tid; i < 6 * PDIM * 2; i += 256) d4[i] = src[i];
    }

    // per-lane weights (72 regs) + corrections (9 regs) + alpha
    const int o = wid * 32 + lane;
    uint32_t wr[9][8];
#pragma unroll
    for (int t = 0; t < 9; t++) {
        const uint4* wp = (const uint4*)(g_w + (o * 9 + t) * 8);
        uint4 q0 = __ldg(wp), q1 = __ldg(wp + 1);
        wr[t][0] = q0.x; wr[t][1] = q0.y; wr[t][2] = q0.z; wr[t][3] = q0.w;
        wr[t][4] = q1.x; wr[t][5] = q1.y; wr[t][6] = q1.z; wr[t][7] = q1.w;
    }
    int corr[9];
#pragma unroll
    for (int t = 0; t < 9; t++) corr[t] = __ldg(g_corr + o * 9 + t);
    const float av = __ldg(alpha + o);

    __syncthreads();

    float* stage = (float*)(smem + SM_STAGE) + wid * (32 * 29);
    const uint32_t* ab = (const uint32_t*)(smem + SM_ABITS);

    for (int ry = 0; ry < 4; ry++) {
        const int y = r0 + ry;

        // row-uniform pad corrections
        const int rowc = (y == 0)  ? (corr[0] + corr[1] + corr[2])
                       : (y == 27) ? (corr[6] + corr[7] + corr[8]) : 0;
        int c0  = corr[0] + corr[3] + corr[6];
        int c27 = corr[2] + corr[5] + corr[8];
        if (y == 0)  { c0 -= corr[0]; c27 -= corr[2]; }
        if (y == 27) { c0 -= corr[6]; c27 -= corr[8]; }

        const uint4* row0 = (const uint4*)(ab + (ry + 0) * PDIM * 8);
        const uint4* row1 = (const uint4*)(ab + (ry + 1) * PDIM * 8);
        const uint4* row2 = (const uint4*)(ab + (ry + 2) * PDIM * 8);

        // branch-free 9-tap body (padded image); x indexes padded cols x..x+2
        auto body = [&](int x, int corrsum) {
            int m0 = 0, m1 = 0, m2 = 0;
#pragma unroll
            for (int kw = 0; kw < 3; kw++) {
                const uint4* p0 = row0 + (x + kw) * 2;
                const uint4* p1 = row1 + (x + kw) * 2;
                const uint4* p2 = row2 + (x + kw) * 2;
                uint4 a0 = p0[0], a1 = p0[1];
                m0 += __popc(a0.x ^ wr[kw][0]) + __popc(a0.y ^ wr[kw][1]);
                m0 += __popc(a0.z ^ wr[kw][2]) + __popc(a0.w ^ wr[kw][3]);
                m0 += __popc(a1.x ^ wr[kw][4]) + __popc(a1.y ^ wr[kw][5]);
                m0 += __popc(a1.z ^ wr[kw][6]) + __popc(a1.w ^ wr[kw][7]);
                uint4 b0 = p1[0], b1 = p1[1];
                m1 += __popc(b0.x ^ wr[3 + kw][0]) + __popc(b0.y ^ wr[3 + kw][1]);
                m1 += __popc(b0.z ^ wr[3 + kw][2]) + __popc(b0.w ^ wr[3 + kw][3]);
                m1 += __popc(b1.x ^ wr[3 + kw][4]) + __popc(b1.y ^ wr[3 + kw][5]);
                m1 += __popc(b1.z ^ wr[3 + kw][6]) + __popc(b1.w ^ wr[3 + kw][7]);
                uint4 c0v = p2[0], c1v = p2[1];
                m2 += __popc(c0v.x ^ wr[6 + kw][0]) + __popc(c0v.y ^ wr[6 + kw][1]);
                m2 += __popc(c0v.z ^ wr[6 + kw][2]) + __popc(c0v.w ^ wr[6 + kw][3]);
                m2 += __popc(c1v.x ^ wr[6 + kw][4]) + __popc(c1v.y ^ wr[6 + kw][5]);
                m2 += __popc(c1v.z ^ wr[6 + kw][6]) + __popc(c1v.w ^ wr[6 + kw][7]);
            }
            const int val = 2304 - 2 * (m0 + m1 + m2) - corrsum;
            stage[lane * 29 + x] = av * (float)val;
        };

        body(0, rowc + c0);
#pragma unroll 2
        for (int x = 1; x < 27; x++) body(x, rowc);
        body(27, rowc + c27);

        __syncwarp();
        // coalesced writeback: lanes sweep x, loop over 32 outch
        float* outb = out + ((size_t)(b * COUT + wid * 32) * HW + y) * HW;
        if (lane < HW) {
#pragma unroll 4
            for (int oo = 0; oo < 32; oo++)
                outb[(size_t)oo * NPIX + lane] = stage[oo * 29 + lane];
        }
        __syncwarp();
    }
}

// ---------------------------------------------------------------------------
extern "C" void kernel_launch(void* const* d_in, const int* in_sizes, int n_in,
                              void* d_out, int out_size)
{
    const float* x  = (const float*)d_in[0];
    const float* M  = (const float*)d_in[1];
    const float* Z  = (const float*)d_in[2];
    const float* al = (const float*)d_in[3];
    const float* rv = (const float*)d_in[4];

    cudaFuncSetAttribute(conv_pop_kernel,
                         cudaFuncAttributeMaxDynamicSharedMemorySize, SM_TOTAL);

    wbits_kernel<<<COUT, CIN>>>(M, Z, rv);
    abits_kernel<<<225, 256>>>(x);
    conv_pop_kernel<<<Bc * 7, 256, SM_TOTAL>>>(al, (float*)d_out);
}

// round 7
// speedup vs baseline: 2.2115x; 1.0004x over previous
#include <cuda_runtime.h>
#include <stdint.h>

#define Bc    64
#define CIN   256
#define COUT  256
#define HW    28
#define NPIX  (HW*HW)            // 784
#define NW    (COUT*CIN*9)       // 589824
#define KK    8
#define PDIM  30
#define PPIX  (PDIM*PDIM)        // 900

// ---------------- device scratch ----------------
__device__ __align__(16) uint32_t g_w[COUT * 9 * 8];          // [o][t][cw] sign bits
__device__ int                    g_corr[COUT * 9];           // 256 - 2*popc(w[o][t])
__device__ __align__(16) uint32_t g_pabits[(size_t)Bc * PPIX * 8]; // padded bit image

// ---------------------------------------------------------------------------
// Kernel 1: weights -> packed sign bits + per-(o,t) pad correction.
// grid <<<256, 256>>>
// ---------------------------------------------------------------------------
__global__ void wbits_kernel(const float* __restrict__ M, const float* __restrict__ Z,
                             const float* __restrict__ rv)
{
    __shared__ int sP[9];
    const int o    = blockIdx.x;
    const int c    = threadIdx.x;
    const int lane = c & 31;
    const int cw   = c >> 5;

    if (c < 9) sP[c] = 0;
    __syncthreads();

    float rvl[KK];
#pragma unroll
    for (int k = 0; k < KK; k++) rvl[k] = __ldg(rv + k);

    const int base = (o * CIN + c) * 9;
    float wv[9];
#pragma unroll
    for (int j = 0; j < 9; j++) wv[j] = M[base + j];
#pragma unroll
    for (int k = 0; k < KK; k++) {
        const float* zp = Z + (size_t)k * NW + base;
#pragma unroll
        for (int j = 0; j < 9; j++) wv[j] += rvl[k] * zp[j];
    }

#pragma unroll
    for (int j = 0; j < 9; j++) {
        unsigned bit  = __float_as_uint(wv[j]) >> 31;
        unsigned mask = __ballot_sync(0xffffffffu, bit);
        if (lane == 0) {
            g_w[(o * 9 + j) * 8 + cw] = mask;
            atomicAdd(&sP[j], __popc(mask));
        }
    }
    __syncthreads();
    if (c < 9) g_corr[o * 9 + c] = 256 - 2 * sP[c];
}

// ---------------------------------------------------------------------------
// Kernel 2: activations -> zero-padded packed bit image [b][pp][8]
// grid <<<225, 256>>>
// ---------------------------------------------------------------------------
__global__ void abits_kernel(const float* __restrict__ x)
{
    const int gid = blockIdx.x * 256 + threadIdx.x;
    const int b  = gid / PPIX;
    const int pp = gid - b * PPIX;
    const int py = pp / PDIM;
    const int px = pp - py * PDIM;

    uint4* dst = (uint4*)(g_pabits + ((size_t)b * PPIX + pp) * 8);

    if (py == 0 || py == PDIM - 1 || px == 0 || px == PDIM - 1) {
        uint4 z = make_uint4(0, 0, 0, 0);
        dst[0] = z; dst[1] = z;
        return;
    }
    const float* xp = x + (size_t)b * CIN * NPIX + (py - 1) * HW + (px - 1);
    uint32_t w[8];
#pragma unroll
    for (int cw = 0; cw < 8; cw++) {
        uint32_t m = 0;
#pragma unroll
        for (int j = 0; j < 32; j++) {
            uint32_t s = __float_as_uint(xp[(size_t)(cw * 32 + j) * NPIX]) >> 31;
            m |= s << j;
        }
        w[cw] = m;
    }
    dst[0] = make_uint4(w[0], w[1], w[2], w[3]);
    dst[1] = make_uint4(w[4], w[5], w[6], w[7]);
}

// ---------------------------------------------------------------------------
// Kernel 3: XNOR-popcount conv, tap-outer / x-inner with 28 row accumulators.
// CTA = (image b, 4-row band). 8 warps; warp = 32-outch group, lane = outch.
// grid <<<448, 256, 35456>>>
// ---------------------------------------------------------------------------
#define SM_ABITS 0                      // 6 rows x 30 px x 32B = 5760
#define SM_STAGE 5760                   // 8 warps x 32 x 29 floats = 29696
#define SM_TOTAL (5760 + 29696)

__global__ void __launch_bounds__(256)
conv_pop_kernel(const float* __restrict__ alpha, float* __restrict__ out)
{
    extern __shared__ __align__(16) uint8_t smem[];

    const int tid  = threadIdx.x;
    const int wid  = tid >> 5;
    const int lane = tid & 31;

    const int b      = blockIdx.x / 7;
    const int blkrow = blockIdx.x - b * 7;
    const int r0     = blkrow * 4;

    // cooperative load: padded rows r0..r0+5 (contiguous)
    {
        const uint4* src = (const uint4*)(g_pabits + ((size_t)b * PPIX + r0 * PDIM) * 8);
        uint4* d4 = (uint4*)(smem + SM_ABITS);
        for (int i = tid; i < 6 * PDIM * 2; i += 256) d4[i] = src[i];
    }

    const int o = wid * 32 + lane;
    int corr[9];
#pragma unroll
    for (int t = 0; t < 9; t++) corr[t] = __ldg(g_corr + o * 9 + t);
    const float av = __ldg(alpha + o);
    const uint4* wbase = (const uint4*)(g_w + o * 72);

    __syncthreads();

    float* stage = (float*)(smem + SM_STAGE) + wid * (32 * 29);
    const uint32_t* ab = (const uint32_t*)(smem + SM_ABITS);

    for (int ry = 0; ry < 4; ry++) {
        const int y = r0 + ry;

        int acc[28];
#pragma unroll
        for (int x = 0; x < 28; x++) acc[x] = 0;

        // tap-outer loops (dynamic -> small code), x-inner fully unrolled
        const uint4* wp = wbase;
#pragma unroll 1
        for (int kh = 0; kh < 3; kh++) {
#pragma unroll 1
            for (int kw = 0; kw < 3; kw++) {
                const uint4* rowp = (const uint4*)(ab + ((ry + kh) * PDIM + kw) * 8);
                const uint4 w0 = __ldg(wp);
                const uint4 w1 = __ldg(wp + 1);
                wp += 2;
#pragma unroll
                for (int x = 0; x < 28; x++) {
                    const uint4 a0 = rowp[x * 2];
                    const uint4 a1 = rowp[x * 2 + 1];
                    acc[x] += __popc(a0.x ^ w0.x) + __popc(a0.y ^ w0.y)
                            + __popc(a0.z ^ w0.z) + __popc(a0.w ^ w0.w)
                            + __popc(a1.x ^ w1.x) + __popc(a1.y ^ w1.y)
                            + __popc(a1.z ^ w1.z) + __popc(a1.w ^ w1.w);
                }
            }
        }

        // pad corrections (row-uniform + column edges)
        const int rowc = (y == 0)  ? (corr[0] + corr[1] + corr[2])
                       : (y == 27) ? (corr[6] + corr[7] + corr[8]) : 0;
        int c0  = corr[0] + corr[3] + corr[6];
        int c27 = corr[2] + corr[5] + corr[8];
        if (y == 0)  { c0 -= corr[0]; c27 -= corr[2]; }
        if (y == 27) { c0 -= corr[6]; c27 -= corr[8]; }

#pragma unroll
        for (int x = 0; x < 28; x++) {
            int cs = rowc;
            if (x == 0)  cs += c0;
            if (x == 27) cs += c27;
            stage[lane * 29 + x] = av * (float)(2304 - 2 * acc[x] - cs);
        }

        __syncwarp();
        float* outb = out + ((size_t)(b * COUT + wid * 32) * HW + y) * HW;
        if (lane < HW) {
#pragma unroll 4
            for (int oo = 0; oo < 32; oo++)
                outb[(size_t)oo * NPIX + lane] = stage[oo * 29 + lane];
        }
        __syncwarp();
    }
}

// ---------------------------------------------------------------------------
extern "C" void kernel_launch(void* const* d_in, const int* in_sizes, int n_in,
                              void* d_out, int out_size)
{
    const float* x  = (const float*)d_in[0];
    const float* M  = (const float*)d_in[1];
    const float* Z  = (const float*)d_in[2];
    const float* al = (const float*)d_in[3];
    const float* rv = (const float*)d_in[4];

    cudaFuncSetAttribute(conv_pop_kernel,
                         cudaFuncAttributeMaxDynamicSharedMemorySize, SM_TOTAL);

    wbits_kernel<<<COUT, CIN>>>(M, Z, rv);
    abits_kernel<<<225, 256>>>(x);
    conv_pop_kernel<<<Bc * 7, 256, SM_TOTAL>>>(al, (float*)d_out);
}